// round 4
// baseline (speedup 1.0000x reference)
#include <cuda_runtime.h>

#define NN      96
#define GRIDN   9216      // NN*NN
#define HIDD    9984      // GRIDN + 8*NN
#define OUTD    9600      // GRIDN + 4*NN
#define BATCH   256
#define INPD    768
#define KDIM    384
#define HPI     1.5707963267948966f

// Static device scratch.
__device__ int   g_cols[OUTD * 5];
__device__ float g_vals[OUTD * 5];
__device__ float g_hid[(size_t)BATCH * HIDD];   // 10.2 MB scratch for hid

// ---------------------------------------------------------------------------
// Build sparse W2_dyn from Beta / W2_fixed using the known grid structure.
// ---------------------------------------------------------------------------
__global__ void build_w2_kernel(const float* __restrict__ Beta,
                                const float* __restrict__ W2f) {
    int r = blockIdx.x * 256 + threadIdx.x;
    if (r >= OUTD) return;
    const float* Br = Beta + (size_t)r * HIDD;
    const float* Fr = W2f  + (size_t)r * HIDD;
    int c[5]; float v[5];
    if (r < GRIDN) {
        int i = r / NN, j = r % NN;
        c[0] = r; v[0] = Fr[r];                                    // diagonal
        if (j > 0)      { c[1] = r - 1;              v[1] = Fr[c[1]]; }
        else            { c[1] = GRIDN + 2*NN + i;   v[1] = atanf(Br[c[1]]) + HPI; }
        if (j < NN - 1) { c[2] = r + 1;              v[2] = atanf(Br[c[2]]) + HPI; }
        else            { c[2] = GRIDN + 3*NN + i;   v[2] = atanf(Br[c[2]]) + HPI; }
        if (i > 0)      { c[3] = r - NN;             v[3] = Fr[c[3]]; }
        else            { c[3] = GRIDN + j;          v[3] = atanf(Br[c[3]]) + HPI; }
        if (i < NN - 1) { c[4] = r + NN;             v[4] = atanf(Br[c[4]]) + HPI; }
        else            { c[4] = GRIDN + NN + j;     v[4] = atanf(Br[c[4]]) + HPI; }
    } else {
        int g = r - GRIDN;
        int node;
        if      (g < NN)     node = g;                              // top
        else if (g < 2 * NN) node = (NN - 1) * NN + (g - NN);       // bottom
        else if (g < 3 * NN) node = (g - 2 * NN) * NN;              // left
        else                 node = (g - 3 * NN) * NN + (NN - 1);   // right
        c[0] = r;         v[0] = Fr[r];
        c[1] = node;      v[1] = Fr[node];
        c[2] = OUTD + g;  v[2] = Fr[OUTD + g];
        c[3] = 0;         v[3] = 0.0f;
        c[4] = 0;         v[4] = 0.0f;
    }
#pragma unroll
    for (int k = 0; k < 5; k++) {
        g_cols[r * 5 + k] = c[k];
        g_vals[r * 5 + k] = v[k];
    }
}

// ---------------------------------------------------------------------------
// g_hid[:, :9216] = x[:, :384] @ W1[:9216, :384]^T
// Tiled fp32 GEMM: BM=64, BN=64, BK=16, 256 threads, 4x4 per thread.
// ---------------------------------------------------------------------------
__global__ void gemm_hid_kernel(const float* __restrict__ X,
                                const float* __restrict__ W1) {
    __shared__ float As[16][64];
    __shared__ float Bs[16][64];
    const int t  = threadIdx.x;
    const int tx = t & 15;
    const int ty = t >> 4;
    const int b0 = blockIdx.y * 64;
    const int n0 = blockIdx.x * 64;

    float acc[4][4] = {};
    for (int k0 = 0; k0 < KDIM; k0 += 16) {
#pragma unroll
        for (int i = 0; i < 4; i++) {
            int idx = t + i * 256;
            int kk  = idx & 15;
            int mm  = idx >> 4;
            As[kk][mm] = X[(size_t)(b0 + mm) * INPD + k0 + kk];
            Bs[kk][mm] = W1[(size_t)(n0 + mm) * INPD + k0 + kk];
        }
        __syncthreads();
#pragma unroll
        for (int kk = 0; kk < 16; kk++) {
            float4 a4 = *(const float4*)&As[kk][ty * 4];
            float4 b4 = *(const float4*)&Bs[kk][tx * 4];
            float av[4] = {a4.x, a4.y, a4.z, a4.w};
            float bv[4] = {b4.x, b4.y, b4.z, b4.w};
#pragma unroll
            for (int p = 0; p < 4; p++)
#pragma unroll
                for (int q = 0; q < 4; q++)
                    acc[p][q] += av[p] * bv[q];
        }
        __syncthreads();
    }
#pragma unroll
    for (int p = 0; p < 4; p++) {
        int b = b0 + ty * 4 + p;
        float* o = g_hid + (size_t)b * HIDD + n0 + tx * 4;
#pragma unroll
        for (int q = 0; q < 4; q++) o[q] = acc[p][q];
    }
}

// ---------------------------------------------------------------------------
// g_hid[:, 9216:9984] = x  (identity passthrough), float4 vectorized.
// ---------------------------------------------------------------------------
__global__ void copy_x_kernel(const float* __restrict__ X) {
    int b = blockIdx.x;
    int t = threadIdx.x;                 // 0..191
    const float4* src = (const float4*)(X + (size_t)b * INPD);
    float4*       dst = (float4*)(g_hid + (size_t)b * HIDD + GRIDN);
    dst[t] = src[t];
}

// ---------------------------------------------------------------------------
// outp[b, r] = sum_k g_vals[r,k] * g_hid[b, g_cols[r,k]]
// Block: 64 rows x 4 batch-lanes; grid (150, 8) => 32 batches per block.
// ---------------------------------------------------------------------------
__global__ void spmm_kernel(float* __restrict__ outp) {
    __shared__ int   sc[64 * 5];
    __shared__ float sv[64 * 5];
    const int r0 = blockIdx.x * 64;
    const int t  = threadIdx.x;
    for (int i = t; i < 320; i += 256) {          // FIXED: cover all 320
        sc[i] = g_cols[r0 * 5 + i];
        sv[i] = g_vals[r0 * 5 + i];
    }
    __syncthreads();
    const int rr = t & 63;
    const int bs = t >> 6;
    const int r  = r0 + rr;
    const int c0 = sc[rr*5+0], c1 = sc[rr*5+1], c2 = sc[rr*5+2],
              c3 = sc[rr*5+3], c4 = sc[rr*5+4];
    const float v0 = sv[rr*5+0], v1 = sv[rr*5+1], v2 = sv[rr*5+2],
                v3 = sv[rr*5+3], v4 = sv[rr*5+4];
    const int bbase = blockIdx.y * 32;
    for (int bi = bs; bi < 32; bi += 4) {
        int b = bbase + bi;
        const float* h = g_hid + (size_t)b * HIDD;
        float acc = v0*h[c0] + v1*h[c1] + v2*h[c2] + v3*h[c3] + v4*h[c4];
        outp[(size_t)b * OUTD + r] = acc;
    }
}

// ---------------------------------------------------------------------------
// Copy hid scratch into the tail of d_out (only launched if it fits).
// ---------------------------------------------------------------------------
__global__ void export_hid_kernel(float* __restrict__ dst) {
    size_t i = (size_t)blockIdx.x * blockDim.x + threadIdx.x;   // float4 index
    const size_t total4 = (size_t)BATCH * HIDD / 4;             // 638976
    if (i < total4) {
        ((float4*)dst)[i] = ((const float4*)g_hid)[i];
    }
}

// ---------------------------------------------------------------------------
extern "C" void kernel_launch(void* const* d_in, const int* in_sizes, int n_in,
                              void* d_out, int out_size) {
    const float* x    = (const float*)d_in[0];  // [256, 768]
    const float* W1   = (const float*)d_in[1];  // [9984, 768]
    const float* Beta = (const float*)d_in[4];  // [9600, 9984]
    const float* W2f  = (const float*)d_in[5];  // [9600, 9984]

    float* outp = (float*)d_out;                // [256, 9600]

    // 1. Sparse W2_dyn values.
    build_w2_kernel<<<(OUTD + 255) / 256, 256>>>(Beta, W2f);

    // 2. Dense block of hid -> scratch.
    dim3 ggrid(GRIDN / 64, BATCH / 64);   // (144, 4)
    gemm_hid_kernel<<<ggrid, 256>>>(x, W1);

    // 3. Passthrough block of hid -> scratch.
    copy_x_kernel<<<BATCH, 192>>>(x);

    // 4. Sparse output GEMM (reads scratch, writes d_out head).
    if (out_size >= BATCH * OUTD) {
        dim3 sgrid(OUTD / 64, 8);         // (150, 8)
        spmm_kernel<<<sgrid, 256>>>(outp);
    }

    // 5. Export hid into d_out tail only if the buffer actually holds it.
    if (out_size >= BATCH * OUTD + BATCH * HIDD) {
        float* hid_dst = (float*)d_out + (size_t)BATCH * OUTD;
        size_t total4 = (size_t)BATCH * HIDD / 4;
        export_hid_kernel<<<(unsigned)((total4 + 255) / 256), 256>>>(hid_dst);
    }
}

// round 6
// speedup vs baseline: 3.8042x; 3.8042x over previous
#include <cuda_runtime.h>
#include <cstdint>

#define NN      96
#define GRIDN   9216
#define HIDD    9984
#define OUTD    9600
#define BATCH   256
#define INPD    768
#define KDIM    384
#define HPI     1.5707963267948966f

// Static device scratch for sparse W2.
__device__ int   g_cols[OUTD * 5];
__device__ float g_vals[OUTD * 5];

// ---------------------------------------------------------------------------
// Build sparse W2_dyn (5 nnz/row) from the known grid structure.
// ---------------------------------------------------------------------------
__global__ void build_w2_kernel(const float* __restrict__ Beta,
                                const float* __restrict__ W2f) {
    int r = blockIdx.x * 256 + threadIdx.x;
    if (r >= OUTD) return;
    const float* Br = Beta + (size_t)r * HIDD;
    const float* Fr = W2f  + (size_t)r * HIDD;
    int c[5]; float v[5];
    if (r < GRIDN) {
        int i = r / NN, j = r % NN;
        c[0] = r; v[0] = Fr[r];
        if (j > 0)      { c[1] = r - 1;              v[1] = Fr[c[1]]; }
        else            { c[1] = GRIDN + 2*NN + i;   v[1] = atanf(Br[c[1]]) + HPI; }
        if (j < NN - 1) { c[2] = r + 1;              v[2] = atanf(Br[c[2]]) + HPI; }
        else            { c[2] = GRIDN + 3*NN + i;   v[2] = atanf(Br[c[2]]) + HPI; }
        if (i > 0)      { c[3] = r - NN;             v[3] = Fr[c[3]]; }
        else            { c[3] = GRIDN + j;          v[3] = atanf(Br[c[3]]) + HPI; }
        if (i < NN - 1) { c[4] = r + NN;             v[4] = atanf(Br[c[4]]) + HPI; }
        else            { c[4] = GRIDN + NN + j;     v[4] = atanf(Br[c[4]]) + HPI; }
    } else {
        int g = r - GRIDN;
        int node;
        if      (g < NN)     node = g;
        else if (g < 2 * NN) node = (NN - 1) * NN + (g - NN);
        else if (g < 3 * NN) node = (g - 2 * NN) * NN;
        else                 node = (g - 3 * NN) * NN + (NN - 1);
        c[0] = r;         v[0] = Fr[r];
        c[1] = node;      v[1] = Fr[node];
        c[2] = OUTD + g;  v[2] = Fr[OUTD + g];
        c[3] = 0;         v[3] = 0.0f;
        c[4] = 0;         v[4] = 0.0f;
    }
#pragma unroll
    for (int k = 0; k < 5; k++) {
        g_cols[r * 5 + k] = c[k];
        g_vals[r * 5 + k] = v[k];
    }
}

// ---------------------------------------------------------------------------
// hid[:, :9216] = x[:, :384] @ W1[:9216, :384]^T  via mma.sync tf32.
// CTA tile: M=128 (batch) x N=128, K looped in chunks of 32.
// 8 warps: 2 (M) x 4 (N); warp tile 64x32; m16n8k8 fragments.
// ---------------------------------------------------------------------------
#define KC     32
#define NCHK   (KDIM / KC)        // 12
#define PITCH  36                 // floats per smem row (bank-conflict free)

__device__ __forceinline__ uint32_t f2tf32(float f) {
    uint32_t o;
    asm("cvt.rna.tf32.f32 %0, %1;" : "=r"(o) : "f"(f));
    return o;
}

__global__ void __launch_bounds__(256, 1)
gemm_tf32_kernel(const float* __restrict__ X, const float* __restrict__ W1,
                 float* __restrict__ hid) {
    __shared__ uint32_t Xs[128 * PITCH];   // 18432 B
    __shared__ uint32_t Ws[128 * PITCH];   // 18432 B

    const int t    = threadIdx.x;
    const int wid  = t >> 5;
    const int lane = t & 31;
    const int g    = lane >> 2;            // group 0..7
    const int tg   = lane & 3;             // 0..3
    const int wm   = wid >> 2;             // 0..1  (M dir)
    const int wn   = wid & 3;              // 0..3  (N dir)
    const int m0   = blockIdx.y * 128;
    const int n0   = blockIdx.x * 128;

    float c[4][4][4];                      // [mf][nf][4]
#pragma unroll
    for (int mf = 0; mf < 4; mf++)
#pragma unroll
        for (int nf = 0; nf < 4; nf++)
#pragma unroll
            for (int q = 0; q < 4; q++) c[mf][nf][q] = 0.0f;

    for (int kc = 0; kc < NCHK; kc++) {
        const int k0 = kc * KC;
        // Stage: 128 rows x 32 floats each for X and W1, tf32-rounded.
        // 128*8=1024 float4 per tile; 256 threads -> 4 float4 each per tile.
#pragma unroll
        for (int i = 0; i < 4; i++) {
            int idx = t + i * 256;         // 0..1023
            int row = idx >> 3;
            int q   = idx & 7;             // float4 index within row
            float4 a = *(const float4*)(X  + (size_t)(m0 + row) * INPD + k0 + q * 4);
            float4 b = *(const float4*)(W1 + (size_t)(n0 + row) * INPD + k0 + q * 4);
            uint32_t* xs = &Xs[row * PITCH + q * 4];
            uint32_t* ws = &Ws[row * PITCH + q * 4];
            xs[0] = f2tf32(a.x); xs[1] = f2tf32(a.y);
            xs[2] = f2tf32(a.z); xs[3] = f2tf32(a.w);
            ws[0] = f2tf32(b.x); ws[1] = f2tf32(b.y);
            ws[2] = f2tf32(b.z); ws[3] = f2tf32(b.w);
        }
        __syncthreads();

#pragma unroll
        for (int ks = 0; ks < 4; ks++) {
            const int k = ks * 8;
            uint32_t a[4][4], b[4][2];
#pragma unroll
            for (int mf = 0; mf < 4; mf++) {
                int row = wm * 64 + mf * 16 + g;
                a[mf][0] = Xs[row * PITCH + k + tg];
                a[mf][1] = Xs[(row + 8) * PITCH + k + tg];
                a[mf][2] = Xs[row * PITCH + k + tg + 4];
                a[mf][3] = Xs[(row + 8) * PITCH + k + tg + 4];
            }
#pragma unroll
            for (int nf = 0; nf < 4; nf++) {
                int col = wn * 32 + nf * 8 + g;
                b[nf][0] = Ws[col * PITCH + k + tg];
                b[nf][1] = Ws[col * PITCH + k + tg + 4];
            }
#pragma unroll
            for (int mf = 0; mf < 4; mf++)
#pragma unroll
                for (int nf = 0; nf < 4; nf++)
                    asm volatile(
                        "mma.sync.aligned.m16n8k8.row.col.f32.tf32.tf32.f32 "
                        "{%0,%1,%2,%3}, {%4,%5,%6,%7}, {%8,%9}, {%0,%1,%2,%3};"
                        : "+f"(c[mf][nf][0]), "+f"(c[mf][nf][1]),
                          "+f"(c[mf][nf][2]), "+f"(c[mf][nf][3])
                        : "r"(a[mf][0]), "r"(a[mf][1]), "r"(a[mf][2]), "r"(a[mf][3]),
                          "r"(b[nf][0]), "r"(b[nf][1]));
        }
        __syncthreads();
    }

    // Epilogue: direct stores, 8-byte (sector-aligned) float2 per fragment row.
#pragma unroll
    for (int mf = 0; mf < 4; mf++) {
        int row = m0 + wm * 64 + mf * 16 + g;
#pragma unroll
        for (int nf = 0; nf < 4; nf++) {
            int col = n0 + wn * 32 + nf * 8 + tg * 2;
            float2* p0 = (float2*)(hid + (size_t)row * HIDD + col);
            float2* p1 = (float2*)(hid + (size_t)(row + 8) * HIDD + col);
            *p0 = make_float2(c[mf][nf][0], c[mf][nf][1]);
            *p1 = make_float2(c[mf][nf][2], c[mf][nf][3]);
        }
    }
}

// ---------------------------------------------------------------------------
// hid[:, 9216:9984] = x
// ---------------------------------------------------------------------------
__global__ void copy_x_kernel(const float* __restrict__ X, float* __restrict__ hid) {
    int b = blockIdx.x;
    int t = threadIdx.x;                 // 0..191
    const float4* src = (const float4*)(X + (size_t)b * INPD);
    float4*       dst = (float4*)(hid + (size_t)b * HIDD + GRIDN);
    dst[t] = src[t];
}

// ---------------------------------------------------------------------------
// outp[b, r] = sum_k vals[r,k] * hid[b, cols[r,k]]
// ---------------------------------------------------------------------------
__global__ void spmm_kernel(const float* __restrict__ hid, float* __restrict__ outp) {
    __shared__ int   sc[64 * 5];
    __shared__ float sv[64 * 5];
    const int r0 = blockIdx.x * 64;
    const int t  = threadIdx.x;
    for (int i = t; i < 320; i += 256) {
        sc[i] = g_cols[r0 * 5 + i];
        sv[i] = g_vals[r0 * 5 + i];
    }
    __syncthreads();
    const int rr = t & 63;
    const int bs = t >> 6;
    const int r  = r0 + rr;
    const int c0 = sc[rr*5+0], c1 = sc[rr*5+1], c2 = sc[rr*5+2],
              c3 = sc[rr*5+3], c4 = sc[rr*5+4];
    const float v0 = sv[rr*5+0], v1 = sv[rr*5+1], v2 = sv[rr*5+2],
                v3 = sv[rr*5+3], v4 = sv[rr*5+4];
    const int bbase = blockIdx.y * 32;
    for (int bi = bs; bi < 32; bi += 4) {
        int b = bbase + bi;
        const float* h = hid + (size_t)b * HIDD;
        float acc = v0*h[c0] + v1*h[c1] + v2*h[c2] + v3*h[c3] + v4*h[c4];
        outp[(size_t)b * OUTD + r] = acc;
    }
}

// ---------------------------------------------------------------------------
extern "C" void kernel_launch(void* const* d_in, const int* in_sizes, int n_in,
                              void* d_out, int out_size) {
    const float* x    = (const float*)d_in[0];
    const float* W1   = (const float*)d_in[1];
    const float* Beta = (const float*)d_in[4];
    const float* W2f  = (const float*)d_in[5];

    if (out_size < BATCH * OUTD + BATCH * HIDD) return;   // layout guard

    float* outp = (float*)d_out;                          // [256, 9600]
    float* hid  = (float*)d_out + (size_t)BATCH * OUTD;   // [256, 9984]

    build_w2_kernel<<<(OUTD + 255) / 256, 256>>>(Beta, W2f);

    dim3 ggrid(GRIDN / 128, BATCH / 128);   // (72, 2)
    gemm_tf32_kernel<<<ggrid, 256>>>(x, W1, hid);

    copy_x_kernel<<<BATCH, 192>>>(x, hid);

    dim3 sgrid(OUTD / 64, 8);               // (150, 8)
    spmm_kernel<<<sgrid, 256>>>(hid, outp);
}

// round 7
// speedup vs baseline: 3.8298x; 1.0067x over previous
#include <cuda_runtime.h>
#include <cstdint>

#define NN      96
#define GRIDN   9216
#define HIDD    9984
#define OUTD    9600
#define BATCH   256
#define INPD    768
#define KDIM    384
#define HPI     1.5707963267948966f

// Static device scratch for sparse W2.
__device__ int   g_cols[OUTD * 5];
__device__ float g_vals[OUTD * 5];

// ---------------------------------------------------------------------------
// Build sparse W2_dyn (5 nnz/row) from the known grid structure.
// ---------------------------------------------------------------------------
__global__ void build_w2_kernel(const float* __restrict__ Beta,
                                const float* __restrict__ W2f) {
    int r = blockIdx.x * 256 + threadIdx.x;
    if (r >= OUTD) return;
    const float* Br = Beta + (size_t)r * HIDD;
    const float* Fr = W2f  + (size_t)r * HIDD;
    int c[5]; float v[5];
    if (r < GRIDN) {
        int i = r / NN, j = r % NN;
        c[0] = r; v[0] = Fr[r];
        if (j > 0)      { c[1] = r - 1;              v[1] = Fr[c[1]]; }
        else            { c[1] = GRIDN + 2*NN + i;   v[1] = atanf(Br[c[1]]) + HPI; }
        if (j < NN - 1) { c[2] = r + 1;              v[2] = atanf(Br[c[2]]) + HPI; }
        else            { c[2] = GRIDN + 3*NN + i;   v[2] = atanf(Br[c[2]]) + HPI; }
        if (i > 0)      { c[3] = r - NN;             v[3] = Fr[c[3]]; }
        else            { c[3] = GRIDN + j;          v[3] = atanf(Br[c[3]]) + HPI; }
        if (i < NN - 1) { c[4] = r + NN;             v[4] = atanf(Br[c[4]]) + HPI; }
        else            { c[4] = GRIDN + NN + j;     v[4] = atanf(Br[c[4]]) + HPI; }
    } else {
        int g = r - GRIDN;
        int node;
        if      (g < NN)     node = g;
        else if (g < 2 * NN) node = (NN - 1) * NN + (g - NN);
        else if (g < 3 * NN) node = (g - 2 * NN) * NN;
        else                 node = (g - 3 * NN) * NN + (NN - 1);
        c[0] = r;         v[0] = Fr[r];
        c[1] = node;      v[1] = Fr[node];
        c[2] = OUTD + g;  v[2] = Fr[OUTD + g];
        c[3] = 0;         v[3] = 0.0f;
        c[4] = 0;         v[4] = 0.0f;
    }
#pragma unroll
    for (int k = 0; k < 5; k++) {
        g_cols[r * 5 + k] = c[k];
        g_vals[r * 5 + k] = v[k];
    }
}

// ---------------------------------------------------------------------------
// hid[:, :9216] = x[:, :384] @ W1[:9216, :384]^T  via mma.sync tf32.
// CTA tile M=128 x N=128, K chunks of 32, register double-buffered staging.
// SMEM layout pre-interleaves K columns (k, k+4 adjacent) so fragment loads
// are LDS.64. PITCH=40 => conflict-free LDS.64 phases.
// ---------------------------------------------------------------------------
#define KC     32
#define NCHK   (KDIM / KC)        // 12
#define PITCH  40

__device__ __forceinline__ uint32_t f2tf32(float f) {
    uint32_t o;
    asm("cvt.rna.tf32.f32 %0, %1;" : "=r"(o) : "f"(f));
    return o;
}

__global__ void __launch_bounds__(256, 1)
gemm_tf32_kernel(const float* __restrict__ X, const float* __restrict__ W1,
                 float* __restrict__ hid) {
    __shared__ uint32_t Xs[128 * PITCH];   // 20480 B
    __shared__ uint32_t Ws[128 * PITCH];   // 20480 B

    const int t    = threadIdx.x;
    const int wid  = t >> 5;
    const int lane = t & 31;
    const int g    = lane >> 2;
    const int tg   = lane & 3;
    const int wm   = wid >> 2;             // 0..1
    const int wn   = wid & 3;              // 0..3
    const int m0   = blockIdx.y * 128;
    const int n0   = blockIdx.x * 128;

    // Staging assignment: 4 units/thread; unit = (tile, row, grp of 8 cols).
    const float* srcp[4];
    uint32_t*    dstp[4];
#pragma unroll
    for (int i = 0; i < 4; i++) {
        int idx  = t + i * 256;            // 0..1023
        int tile = idx >> 9;               // 0 = X, 1 = W1
        int row  = (idx >> 2) & 127;
        int grp  = idx & 3;
        srcp[i] = (tile ? W1 + (size_t)(n0 + row) * INPD
                        : X  + (size_t)(m0 + row) * INPD) + grp * 8;
        dstp[i] = (tile ? Ws : Xs) + row * PITCH + grp * 8;
    }

    float4 lo[4], hi[4];
#pragma unroll
    for (int i = 0; i < 4; i++) {          // prologue: chunk 0
        lo[i] = *(const float4*)(srcp[i]);
        hi[i] = *(const float4*)(srcp[i] + 4);
    }

    float c[4][4][4];
#pragma unroll
    for (int mf = 0; mf < 4; mf++)
#pragma unroll
        for (int nf = 0; nf < 4; nf++)
#pragma unroll
            for (int q = 0; q < 4; q++) c[mf][nf][q] = 0.0f;

    for (int kc = 0; kc < NCHK; kc++) {
        // Store current chunk (interleaved: global k and k+4 adjacent).
#pragma unroll
        for (int i = 0; i < 4; i++) {
            uint32_t* d = dstp[i];
            d[0] = f2tf32(lo[i].x); d[1] = f2tf32(hi[i].x);
            d[2] = f2tf32(lo[i].y); d[3] = f2tf32(hi[i].y);
            d[4] = f2tf32(lo[i].z); d[5] = f2tf32(hi[i].z);
            d[6] = f2tf32(lo[i].w); d[7] = f2tf32(hi[i].w);
        }
        __syncthreads();

        // Prefetch next chunk (latency hidden behind MMAs).
        if (kc + 1 < NCHK) {
            const int off = (kc + 1) * KC;
#pragma unroll
            for (int i = 0; i < 4; i++) {
                lo[i] = *(const float4*)(srcp[i] + off);
                hi[i] = *(const float4*)(srcp[i] + off + 4);
            }
        }

#pragma unroll
        for (int ks = 0; ks < 4; ks++) {
            const int kb = ks * 8 + tg * 2;
            uint2 a0[4], a1[4], bv[4];
#pragma unroll
            for (int mf = 0; mf < 4; mf++) {
                int row = wm * 64 + mf * 16 + g;
                a0[mf] = *(const uint2*)&Xs[row * PITCH + kb];        // {k, k+4}
                a1[mf] = *(const uint2*)&Xs[(row + 8) * PITCH + kb];
            }
#pragma unroll
            for (int nf = 0; nf < 4; nf++) {
                int col = wn * 32 + nf * 8 + g;
                bv[nf] = *(const uint2*)&Ws[col * PITCH + kb];
            }
#pragma unroll
            for (int mf = 0; mf < 4; mf++)
#pragma unroll
                for (int nf = 0; nf < 4; nf++)
                    asm volatile(
                        "mma.sync.aligned.m16n8k8.row.col.f32.tf32.tf32.f32 "
                        "{%0,%1,%2,%3}, {%4,%5,%6,%7}, {%8,%9}, {%0,%1,%2,%3};"
                        : "+f"(c[mf][nf][0]), "+f"(c[mf][nf][1]),
                          "+f"(c[mf][nf][2]), "+f"(c[mf][nf][3])
                        : "r"(a0[mf].x), "r"(a1[mf].x), "r"(a0[mf].y), "r"(a1[mf].y),
                          "r"(bv[nf].x), "r"(bv[nf].y));
        }
        __syncthreads();
    }

    // Epilogue: 8-byte sector-aligned float2 stores.
#pragma unroll
    for (int mf = 0; mf < 4; mf++) {
        int row = m0 + wm * 64 + mf * 16 + g;
#pragma unroll
        for (int nf = 0; nf < 4; nf++) {
            int col = n0 + wn * 32 + nf * 8 + tg * 2;
            float2* p0 = (float2*)(hid + (size_t)row * HIDD + col);
            float2* p1 = (float2*)(hid + (size_t)(row + 8) * HIDD + col);
            *p0 = make_float2(c[mf][nf][0], c[mf][nf][1]);
            *p1 = make_float2(c[mf][nf][2], c[mf][nf][3]);
        }
    }
}

// ---------------------------------------------------------------------------
// hid[:, 9216:9984] = x
// ---------------------------------------------------------------------------
__global__ void copy_x_kernel(const float* __restrict__ X, float* __restrict__ hid) {
    int b = blockIdx.x;
    int t = threadIdx.x;                 // 0..191
    const float4* src = (const float4*)(X + (size_t)b * INPD);
    float4*       dst = (float4*)(hid + (size_t)b * HIDD + GRIDN);
    dst[t] = src[t];
}

// ---------------------------------------------------------------------------
// outp[b, r] = sum_k vals[r,k] * hid[b, cols[r,k]]
// SoA batch unroll: 8 accumulators, 8 independent gathers in flight.
// ---------------------------------------------------------------------------
__global__ void spmm_kernel(const float* __restrict__ hid, float* __restrict__ outp) {
    __shared__ int   sc[64 * 5];
    __shared__ float sv[64 * 5];
    const int r0 = blockIdx.x * 64;
    const int t  = threadIdx.x;
    for (int i = t; i < 320; i += 256) {
        sc[i] = g_cols[r0 * 5 + i];
        sv[i] = g_vals[r0 * 5 + i];
    }
    __syncthreads();
    const int rr = t & 63;
    const int bs = t >> 6;               // 0..3
    const int r  = r0 + rr;
    const int c0 = sc[rr*5+0], c1 = sc[rr*5+1], c2 = sc[rr*5+2],
              c3 = sc[rr*5+3], c4 = sc[rr*5+4];
    const float v0 = sv[rr*5+0], v1 = sv[rr*5+1], v2 = sv[rr*5+2],
                v3 = sv[rr*5+3], v4 = sv[rr*5+4];

    const int bb = blockIdx.y * 32 + bs;           // first batch for this thread
    const float* hb = hid + (size_t)bb * HIDD;
    const size_t ST = (size_t)4 * HIDD;            // batch stride (4 lanes)

    float acc[8];
#pragma unroll
    for (int u = 0; u < 8; u++) acc[u]  = v0 * hb[u * ST + c0];
#pragma unroll
    for (int u = 0; u < 8; u++) acc[u] += v1 * hb[u * ST + c1];
#pragma unroll
    for (int u = 0; u < 8; u++) acc[u] += v2 * hb[u * ST + c2];
#pragma unroll
    for (int u = 0; u < 8; u++) acc[u] += v3 * hb[u * ST + c3];
#pragma unroll
    for (int u = 0; u < 8; u++) acc[u] += v4 * hb[u * ST + c4];

    float* ob = outp + (size_t)bb * OUTD + r;
#pragma unroll
    for (int u = 0; u < 8; u++) ob[u * 4 * OUTD] = acc[u];
}

// ---------------------------------------------------------------------------
extern "C" void kernel_launch(void* const* d_in, const int* in_sizes, int n_in,
                              void* d_out, int out_size) {
    const float* x    = (const float*)d_in[0];
    const float* W1   = (const float*)d_in[1];
    const float* Beta = (const float*)d_in[4];
    const float* W2f  = (const float*)d_in[5];

    if (out_size < BATCH * OUTD + BATCH * HIDD) return;   // layout guard

    float* outp = (float*)d_out;                          // [256, 9600]
    float* hid  = (float*)d_out + (size_t)BATCH * OUTD;   // [256, 9984]

    build_w2_kernel<<<(OUTD + 255) / 256, 256>>>(Beta, W2f);

    dim3 ggrid(GRIDN / 128, BATCH / 128);   // (72, 2)
    gemm_tf32_kernel<<<ggrid, 256>>>(x, W1, hid);

    copy_x_kernel<<<BATCH, 192>>>(x, hid);

    dim3 sgrid(OUTD / 64, 8);               // (150, 8)
    spmm_kernel<<<sgrid, 256>>>(hid, outp);
}